// round 16
// baseline (speedup 1.0000x reference)
#include <cuda_runtime.h>
#include <cuda_bf16.h>
#include <math.h>

// Problem constants
#define BB   2
#define TT   2048
#define EE   1024
#define HH   16
#define HS   64
#define ROWS (BB*TT)          // 4096

// ---------------- device scratch ----------------
__device__ float g_h1[ROWS*EE];
__device__ float g_q [ROWS*EE];
__device__ float g_k [ROWS*EE];
__device__ float g_v [ROWS*EE];
__device__ float g_attn[ROWS*EE];
__device__ float g_sa [ROWS*EE];
__device__ float g_x1 [ROWS*EE];
__device__ float g_h2 [ROWS*EE];
__device__ float g_f1 [ROWS*4*EE];
__device__ float g_f2 [ROWS*2*EE];
__device__ float g_f3 [ROWS*EE];
__device__ float g_L  [BB*HH*TT];
// tf32-rounded weight copies
__device__ float g_wq_r [HH*EE*HS];
__device__ float g_wk_r [HH*EE*HS];
__device__ float g_wv_r [HH*EE*HS];
__device__ float g_wp_r [EE*EE];
__device__ float g_wga_r[EE*EE];
__device__ float g_w1_r [EE*4*EE];
__device__ float g_w2_r [4*EE*2*EE];
__device__ float g_w3_r [2*EE*EE];
__device__ float g_wgf_r[EE*EE];

// ---------------- tf32 / cp.async helpers ----------------
__device__ __forceinline__ unsigned f2tf32(float f) {
    unsigned u;
    asm("cvt.rna.tf32.f32 %0, %1;" : "=r"(u) : "f"(f));
    return u;
}
__device__ __forceinline__ float rnd_tf32(float f) {
    return __uint_as_float(f2tf32(f));
}

__device__ __forceinline__ void mma_tf32(float* c, const unsigned* a,
                                         const unsigned* b) {
    asm volatile(
        "mma.sync.aligned.m16n8k8.row.col.f32.tf32.tf32.f32 "
        "{%0,%1,%2,%3}, {%4,%5,%6,%7}, {%8,%9}, {%0,%1,%2,%3};"
        : "+f"(c[0]), "+f"(c[1]), "+f"(c[2]), "+f"(c[3])
        : "r"(a[0]), "r"(a[1]), "r"(a[2]), "r"(a[3]),
          "r"(b[0]), "r"(b[1]));
}

__device__ __forceinline__ void cp_async16(void* smem_dst, const void* gsrc) {
    unsigned s = (unsigned)__cvta_generic_to_shared(smem_dst);
    asm volatile("cp.async.cg.shared.global [%0], [%1], 16;"
                 :: "r"(s), "l"(gsrc));
}
#define CP_COMMIT() asm volatile("cp.async.commit_group;" ::: "memory")
#define CP_WAIT0()  asm volatile("cp.async.wait_group 0;" ::: "memory")
#define CP_WAIT1()  asm volatile("cp.async.wait_group 1;" ::: "memory")

// ---------------- weight pre-rounding (tf32 rna) ----------------
__global__ void cvt_tf32_kernel(const float* __restrict__ in,
                                float* __restrict__ out, int n4) {
    int i = blockIdx.x * blockDim.x + threadIdx.x;
    if (i < n4) {
        float4 v = ((const float4*)in)[i];
        v.x = rnd_tf32(v.x); v.y = rnd_tf32(v.y);
        v.z = rnd_tf32(v.z); v.w = rnd_tf32(v.w);
        ((float4*)out)[i] = v;
    }
}

// ---------------- LayerNorm (tf32-rounded output) ----------------
__global__ void ln_kernel(const float* __restrict__ x,
                          const float* __restrict__ g,
                          const float* __restrict__ b,
                          float* __restrict__ out) {
    int row = blockIdx.x;
    int tid = threadIdx.x;
    const float* xr = x + (size_t)row * EE;
    float4 v = *(const float4*)(xr + tid * 4);
    float s  = v.x + v.y + v.z + v.w;
    float ss = v.x*v.x + v.y*v.y + v.z*v.z + v.w*v.w;
    __shared__ float sm[32], sm2[32];
    int lane = tid & 31, warp = tid >> 5;
    #pragma unroll
    for (int o = 16; o > 0; o >>= 1) {
        s  += __shfl_down_sync(0xffffffffu, s,  o);
        ss += __shfl_down_sync(0xffffffffu, ss, o);
    }
    if (lane == 0) { sm[warp] = s; sm2[warp] = ss; }
    __syncthreads();
    if (warp == 0) {
        float a = (lane < 8) ? sm[lane]  : 0.f;
        float c = (lane < 8) ? sm2[lane] : 0.f;
        #pragma unroll
        for (int o = 4; o > 0; o >>= 1) {
            a += __shfl_down_sync(0xffffffffu, a, o);
            c += __shfl_down_sync(0xffffffffu, c, o);
        }
        if (lane == 0) { sm[0] = a; sm2[0] = c; }
    }
    __syncthreads();
    float mu  = sm[0]  * (1.0f / EE);
    float var = sm2[0] * (1.0f / EE) - mu * mu;
    float rstd = rsqrtf(var + 1e-5f);
    float4 gg = *(const float4*)(g + tid * 4);
    float4 bb = *(const float4*)(b + tid * 4);
    float4 o;
    o.x = rnd_tf32((v.x - mu) * rstd * gg.x + bb.x);
    o.y = rnd_tf32((v.y - mu) * rstd * gg.y + bb.y);
    o.z = rnd_tf32((v.z - mu) * rstd * gg.z + bb.z);
    o.w = rnd_tf32((v.w - mu) * rstd * gg.w + bb.w);
    *(float4*)(out + (size_t)row * EE + tid * 4) = o;
}

// ---------------- QKV GEMM (BM=128, BN=64, round-14 proven) ----------------
#define BMM 128
#define BKK 16
#define STG 3

__global__ void __launch_bounds__(128, 3)
mma_gemm_qkv(const float* __restrict__ A,
             const float* __restrict__ B0, const float* __restrict__ B1,
             const float* __restrict__ B2,
             float* __restrict__ C0, float* __restrict__ C1,
             float* __restrict__ C2,
             int K, size_t bStrideZ, size_t cStrideZ) {
    constexpr int BN = 64;
    constexpr int THREADS = 128;
    constexpr int AP  = 20;
    constexpr int BP  = BN + 8;
    constexpr int ASZ = BMM * AP;
    constexpr int BSZ = BKK * BP;
    constexpr int LA  = 512 / THREADS;
    constexpr int LB  = (BKK * BN / 4) / THREADS;
    constexpr int BNQ = BN / 4;
    constexpr int N = BN;

    extern __shared__ float dynsm[];
    float* As = dynsm;
    float* Bs = dynsm + STG * ASZ;

    int zz = blockIdx.z;
    int which = zz >> 4, head = zz & 15;
    const float* Bsel = (which == 0) ? B0 : ((which == 1) ? B1 : B2);
    float*       Csel = (which == 0) ? C0 : ((which == 1) ? C1 : C2);
    const float* Bp = Bsel + (size_t)head * bStrideZ;
    float*       Cp = Csel + (size_t)head * cStrideZ;

    int m0 = blockIdx.y * BMM;
    int tid  = threadIdx.x;
    int lane = tid & 31, warp = tid >> 5;
    int wm = warp >> 1, wn = warp & 1;

    float acc[4][4][4];
    #pragma unroll
    for (int i = 0; i < 4; i++)
        #pragma unroll
        for (int j = 0; j < 4; j++)
            #pragma unroll
            for (int l = 0; l < 4; l++) acc[i][j][l] = 0.f;

    auto stage = [&](int s, int k0) {
        #pragma unroll
        for (int i = 0; i < LA; i++) {
            int idx = tid + i * THREADS;
            int r = idx >> 2, c4 = idx & 3;
            cp_async16(&As[s * ASZ + r * AP + c4 * 4],
                       A + (size_t)(m0 + r) * K + k0 + c4 * 4);
        }
        #pragma unroll
        for (int i = 0; i < LB; i++) {
            int idx = tid + i * THREADS;
            int r = idx / BNQ, c4 = idx % BNQ;
            cp_async16(&Bs[s * BSZ + r * BP + c4 * 4],
                       Bp + (size_t)(k0 + r) * N + c4 * 4);
        }
    };

    int nk = K / BKK;
    stage(0, 0); CP_COMMIT();
    stage(1, BKK); CP_COMMIT();

    for (int it = 0; it < nk; it++) {
        CP_WAIT1();
        __syncthreads();
        if (it + 2 < nk) stage((it + 2) % STG, (it + 2) * BKK);
        CP_COMMIT();

        const float* Asb = As + (it % STG) * ASZ;
        const float* Bsb = Bs + (it % STG) * BSZ;
        #pragma unroll
        for (int ks = 0; ks < BKK; ks += 8) {
            int lk = ks + (lane & 3);
            int lm = lane >> 2;
            unsigned a[4][4], b[4][2];
            #pragma unroll
            for (int mi = 0; mi < 4; mi++) {
                int m = wm * 64 + mi * 16 + lm;
                a[mi][0] = __float_as_uint(Asb[m * AP + lk]);
                a[mi][1] = __float_as_uint(Asb[(m + 8) * AP + lk]);
                a[mi][2] = __float_as_uint(Asb[m * AP + lk + 4]);
                a[mi][3] = __float_as_uint(Asb[(m + 8) * AP + lk + 4]);
            }
            #pragma unroll
            for (int ni = 0; ni < 4; ni++) {
                int n = wn * 32 + ni * 8 + lm;
                b[ni][0] = __float_as_uint(Bsb[lk * BP + n]);
                b[ni][1] = __float_as_uint(Bsb[(lk + 4) * BP + n]);
            }
            #pragma unroll
            for (int mi = 0; mi < 4; mi++)
                #pragma unroll
                for (int ni = 0; ni < 4; ni++)
                    mma_tf32(acc[mi][ni], a[mi], b[ni]);
        }
    }

    int gm = m0 + wm * 64;
    int gn = wn * 32;
    #pragma unroll
    for (int mi = 0; mi < 4; mi++) {
        #pragma unroll
        for (int half = 0; half < 2; half++) {
            int row = gm + mi * 16 + (lane >> 2) + half * 8;
            #pragma unroll
            for (int ni = 0; ni < 4; ni++) {
                int col = gn + ni * 8 + (lane & 3) * 2;
                float v0 = rnd_tf32(acc[mi][ni][half * 2 + 0]);
                float v1 = rnd_tf32(acc[mi][ni][half * 2 + 1]);
                *(float2*)(Cp + (size_t)row * N + col) = make_float2(v0, v1);
            }
        }
    }
}

// ---------------- Big GEMM: BM=256, BN=128, warp tile 64x64 ----------------
// 8 warps (4M x 2N); per k8: 32 LDS words feed 32 MMAs (50% MMA share).
// EPI: 0 bias, 1 gelu+bias, 2 other + sigmoid(+bias)*resid. RC: tf32-round C.
#define BMB 256
#define BNB 128

template<int EPI, int RC>
__global__ void __launch_bounds__(256, 1)
mma_gemm_big(const float* __restrict__ A, const float* __restrict__ Bm,
             const float* __restrict__ bias, float* __restrict__ C,
             int M, int N, int K,
             const float* __restrict__ other, const float* __restrict__ resid) {
    constexpr int AP  = 20;
    constexpr int BP  = BNB + 8;            // 136
    constexpr int ASZ = BMB * AP;           // 5120
    constexpr int BSZ = BKK * BP;           // 2176

    extern __shared__ float dynsm[];
    float* As = dynsm;
    float* Bs = dynsm + STG * ASZ;

    int m0 = blockIdx.y * BMB, n0 = blockIdx.x * BNB;
    int tid  = threadIdx.x;
    int lane = tid & 31, warp = tid >> 5;
    int wm = warp >> 1, wn = warp & 1;

    float acc[4][8][4];
    #pragma unroll
    for (int i = 0; i < 4; i++)
        #pragma unroll
        for (int j = 0; j < 8; j++)
            #pragma unroll
            for (int l = 0; l < 4; l++) acc[i][j][l] = 0.f;

    auto stage = [&](int s, int k0) {
        #pragma unroll
        for (int i = 0; i < 4; i++) {       // A: 1024 float4
            int idx = tid + i * 256;
            int r = idx >> 2, c4 = idx & 3;
            cp_async16(&As[s * ASZ + r * AP + c4 * 4],
                       A + (size_t)(m0 + r) * K + k0 + c4 * 4);
        }
        #pragma unroll
        for (int i = 0; i < 2; i++) {       // B: 512 float4
            int idx = tid + i * 256;
            int r = idx >> 5, c4 = idx & 31;
            cp_async16(&Bs[s * BSZ + r * BP + c4 * 4],
                       Bm + (size_t)(k0 + r) * N + n0 + c4 * 4);
        }
    };

    int nk = K / BKK;
    stage(0, 0); CP_COMMIT();
    stage(1, BKK); CP_COMMIT();

    for (int it = 0; it < nk; it++) {
        CP_WAIT1();
        __syncthreads();
        if (it + 2 < nk) stage((it + 2) % STG, (it + 2) * BKK);
        CP_COMMIT();

        const float* Asb = As + (it % STG) * ASZ;
        const float* Bsb = Bs + (it % STG) * BSZ;
        #pragma unroll
        for (int ks = 0; ks < BKK; ks += 8) {
            int lk = ks + (lane & 3);
            int lm = lane >> 2;
            unsigned a[4][4], b[8][2];
            #pragma unroll
            for (int mi = 0; mi < 4; mi++) {
                int m = wm * 64 + mi * 16 + lm;
                a[mi][0] = __float_as_uint(Asb[m * AP + lk]);
                a[mi][1] = __float_as_uint(Asb[(m + 8) * AP + lk]);
                a[mi][2] = __float_as_uint(Asb[m * AP + lk + 4]);
                a[mi][3] = __float_as_uint(Asb[(m + 8) * AP + lk + 4]);
            }
            #pragma unroll
            for (int ni = 0; ni < 8; ni++) {
                int n = wn * 64 + ni * 8 + lm;
                b[ni][0] = __float_as_uint(Bsb[lk * BP + n]);
                b[ni][1] = __float_as_uint(Bsb[(lk + 4) * BP + n]);
            }
            #pragma unroll
            for (int mi = 0; mi < 4; mi++)
                #pragma unroll
                for (int ni = 0; ni < 8; ni++)
                    mma_tf32(acc[mi][ni], a[mi], b[ni]);
        }
    }

    // ---------------- epilogue ----------------
    int gm = m0 + wm * 64;
    int gn = n0 + wn * 64;
    #pragma unroll
    for (int mi = 0; mi < 4; mi++) {
        #pragma unroll
        for (int half = 0; half < 2; half++) {
            int row = gm + mi * 16 + (lane >> 2) + half * 8;
            #pragma unroll
            for (int ni = 0; ni < 8; ni++) {
                int col = gn + ni * 8 + (lane & 3) * 2;
                float v0 = acc[mi][ni][half * 2 + 0];
                float v1 = acc[mi][ni][half * 2 + 1];
                if (bias) { v0 += bias[col]; v1 += bias[col + 1]; }
                size_t idx = (size_t)row * N + col;
                float2 o;
                if (EPI == 0) {
                    o = make_float2(v0, v1);
                } else if (EPI == 1) {
                    o.x = 0.5f * v0 * (1.0f + erff(v0 * 0.70710678118654752f));
                    o.y = 0.5f * v1 * (1.0f + erff(v1 * 0.70710678118654752f));
                } else {
                    float2 ot = *(const float2*)(other + idx);
                    float2 rs = *(const float2*)(resid + idx);
                    o.x = ot.x + rs.x / (1.0f + __expf(-v0));
                    o.y = ot.y + rs.y / (1.0f + __expf(-v1));
                }
                if (RC) { o.x = rnd_tf32(o.x); o.y = rnd_tf32(o.y); }
                *(float2*)(C + idx) = o;
            }
        }
    }
}

// ==================== MMA attention (unchanged, passing) ====================
#define QP 68
#define KPP 68
#define VPP 72
#define PPP 68

__device__ __forceinline__ void s_tile_mma(const float* __restrict__ Qs,
                                           const float* __restrict__ Ks,
                                           int wm, int wn, int lane,
                                           float acc[4][2][4]) {
    #pragma unroll
    for (int mi = 0; mi < 4; mi++)
        #pragma unroll
        for (int ni = 0; ni < 2; ni++)
            #pragma unroll
            for (int l = 0; l < 4; l++) acc[mi][ni][l] = 0.f;
    int lm = lane >> 2, lk = lane & 3;
    #pragma unroll
    for (int ks = 0; ks < 8; ks++) {
        int kb = ks * 8;
        unsigned a[4][4], b[2][2];
        #pragma unroll
        for (int mi = 0; mi < 4; mi++) {
            int m = wm * 64 + mi * 16 + lm;
            a[mi][0] = __float_as_uint(Qs[m * QP + kb + lk]);
            a[mi][1] = __float_as_uint(Qs[(m + 8) * QP + kb + lk]);
            a[mi][2] = __float_as_uint(Qs[m * QP + kb + lk + 4]);
            a[mi][3] = __float_as_uint(Qs[(m + 8) * QP + kb + lk + 4]);
        }
        #pragma unroll
        for (int ni = 0; ni < 2; ni++) {
            int n = wn * 16 + ni * 8 + lm;
            b[ni][0] = __float_as_uint(Ks[n * KPP + kb + lk]);
            b[ni][1] = __float_as_uint(Ks[n * KPP + kb + lk + 4]);
        }
        #pragma unroll
        for (int mi = 0; mi < 4; mi++)
            #pragma unroll
            for (int ni = 0; ni < 2; ni++)
                mma_tf32(acc[mi][ni], a[mi], b[ni]);
    }
}

__global__ void __launch_bounds__(256)
attn_sum(const float* __restrict__ q, const float* __restrict__ k,
         float* __restrict__ Lb) {
    extern __shared__ float sm[];
    float* Qs   = sm;
    float* Ks   = sm + 128 * QP;
    float* Lred = Ks + 64 * KPP;

    int bh = blockIdx.y;
    int qt = (int)(gridDim.x - 1) - (int)blockIdx.x;
    int b = bh >> 4, h = bh & 15;
    int qbase = qt * 128;
    const float* qg = q + ((size_t)h * ROWS + (size_t)b * TT + qbase) * HS;
    const float* kg = k + ((size_t)h * ROWS + (size_t)b * TT) * HS;

    int tid = threadIdx.x;
    int lane = tid & 31, warp = tid >> 5;
    int wm = warp >> 2, wn = warp & 3;
    int lm = lane >> 2, lk = lane & 3;

    #pragma unroll
    for (int i = 0; i < 8; i++) {
        int idx = tid + i * 256;
        int r = idx >> 4, c4 = idx & 15;
        cp_async16(&Qs[r * QP + c4 * 4], qg + (size_t)r * HS + c4 * 4);
    }
    CP_COMMIT();
    CP_WAIT0();
    __syncthreads();

    float lsum[4][2];
    #pragma unroll
    for (int mi = 0; mi < 4; mi++) { lsum[mi][0] = 0.f; lsum[mi][1] = 0.f; }

    int nkt = 2 * qt + 2;
    for (int kt = 0; kt < nkt; kt++) {
        __syncthreads();
        #pragma unroll
        for (int i = 0; i < 4; i++) {
            int idx = tid + i * 256;
            int r = idx >> 4, c4 = idx & 15;
            cp_async16(&Ks[r * KPP + c4 * 4],
                       kg + (size_t)(kt * 64 + r) * HS + c4 * 4);
        }
        CP_COMMIT();
        CP_WAIT0();
        __syncthreads();

        float acc[4][2][4];
        s_tile_mma(Qs, Ks, wm, wn, lane, acc);
        if (kt < 2 * qt) {
            #pragma unroll
            for (int mi = 0; mi < 4; mi++)
                #pragma unroll
                for (int ni = 0; ni < 2; ni++) {
                    float* c = acc[mi][ni];
                    lsum[mi][0] += __expf(c[0] * 0.125f)
                                 + __expf(c[1] * 0.125f);
                    lsum[mi][1] += __expf(c[2] * 0.125f)
                                 + __expf(c[3] * 0.125f);
                }
        } else {
            #pragma unroll
            for (int mi = 0; mi < 4; mi++) {
                int rq = qbase + wm * 64 + mi * 16 + lm;
                #pragma unroll
                for (int ni = 0; ni < 2; ni++) {
                    int kc = kt * 64 + wn * 16 + ni * 8 + 2 * lk;
                    float* c = acc[mi][ni];
                    if (kc     <= rq)     lsum[mi][0] += __expf(c[0] * 0.125f);
                    if (kc + 1 <= rq)     lsum[mi][0] += __expf(c[1] * 0.125f);
                    if (kc     <= rq + 8) lsum[mi][1] += __expf(c[2] * 0.125f);
                    if (kc + 1 <= rq + 8) lsum[mi][1] += __expf(c[3] * 0.125f);
                }
            }
        }
    }

    #pragma unroll
    for (int mi = 0; mi < 4; mi++)
        #pragma unroll
        for (int hf = 0; hf < 2; hf++) {
            float v = lsum[mi][hf];
            v += __shfl_xor_sync(0xffffffffu, v, 1);
            v += __shfl_xor_sync(0xffffffffu, v, 2);
            if (lk == 0)
                Lred[(wm * 64 + mi * 16 + lm + hf * 8) * 4 + wn] = v;
        }
    __syncthreads();
    if (tid < 128) {
        float l = Lred[tid * 4] + Lred[tid * 4 + 1] +
                  Lred[tid * 4 + 2] + Lred[tid * 4 + 3];
        Lb[(size_t)bh * TT + qbase + tid] = l;
    }
}

__global__ void __launch_bounds__(256)
attn_out(const float* __restrict__ q, const float* __restrict__ k,
         const float* __restrict__ v, const float* __restrict__ Lb,
         float* __restrict__ wei, float* __restrict__ attn) {
    extern __shared__ float sm[];
    float* Qs = sm;
    float* Ks = Qs + 128 * QP;
    float* Vs = Ks + 64 * KPP;
    float* Ps = Vs + 64 * VPP;

    int bh = blockIdx.y;
    int qt = (int)(gridDim.x - 1) - (int)blockIdx.x;
    int b = bh >> 4, h = bh & 15;
    int qbase = qt * 128;
    const float* qg = q + ((size_t)h * ROWS + (size_t)b * TT + qbase) * HS;
    const float* kg = k + ((size_t)h * ROWS + (size_t)b * TT) * HS;
    const float* vg = v + ((size_t)h * ROWS + (size_t)b * TT) * HS;
    float* weib = wei + ((size_t)bh * TT + qbase) * TT;

    int tid = threadIdx.x;
    int lane = tid & 31, warp = tid >> 5;
    int wm = warp >> 2, wn = warp & 3;
    int lm = lane >> 2, lk = lane & 3;

    #pragma unroll
    for (int i = 0; i < 8; i++) {
        int idx = tid + i * 256;
        int r = idx >> 4, c4 = idx & 15;
        cp_async16(&Qs[r * QP + c4 * 4], qg + (size_t)r * HS + c4 * 4);
    }
    CP_COMMIT();

    float invl[4][2];
    #pragma unroll
    for (int mi = 0; mi < 4; mi++)
        #pragma unroll
        for (int hf = 0; hf < 2; hf++)
            invl[mi][hf] = 1.0f /
                Lb[(size_t)bh * TT + qbase + wm * 64 + mi * 16 + lm + hf * 8];

    float oacc[4][2][4];
    #pragma unroll
    for (int mi = 0; mi < 4; mi++)
        #pragma unroll
        for (int ni = 0; ni < 2; ni++)
            #pragma unroll
            for (int l = 0; l < 4; l++) oacc[mi][ni][l] = 0.f;

    CP_WAIT0();
    __syncthreads();

    int nkt = 2 * qt + 2;
    for (int kt = 0; kt < nkt; kt++) {
        __syncthreads();
        #pragma unroll
        for (int i = 0; i < 4; i++) {
            int idx = tid + i * 256;
            int r = idx >> 4, c4 = idx & 15;
            cp_async16(&Ks[r * KPP + c4 * 4],
                       kg + (size_t)(kt * 64 + r) * HS + c4 * 4);
            cp_async16(&Vs[r * VPP + c4 * 4],
                       vg + (size_t)(kt * 64 + r) * HS + c4 * 4);
        }
        CP_COMMIT();
        CP_WAIT0();
        __syncthreads();

        float acc[4][2][4];
        s_tile_mma(Qs, Ks, wm, wn, lane, acc);

        if (kt < 2 * qt) {
            #pragma unroll
            for (int mi = 0; mi < 4; mi++) {
                int r0 = wm * 64 + mi * 16 + lm;
                #pragma unroll
                for (int ni = 0; ni < 2; ni++) {
                    int cl = wn * 16 + ni * 8 + 2 * lk;
                    float* c = acc[mi][ni];
                    float2 p0, p1;
                    p0.x = rnd_tf32(__expf(c[0] * 0.125f) * invl[mi][0]);
                    p0.y = rnd_tf32(__expf(c[1] * 0.125f) * invl[mi][0]);
                    p1.x = rnd_tf32(__expf(c[2] * 0.125f) * invl[mi][1]);
                    p1.y = rnd_tf32(__expf(c[3] * 0.125f) * invl[mi][1]);
                    *(float2*)&Ps[r0 * PPP + cl] = p0;
                    *(float2*)&Ps[(r0 + 8) * PPP + cl] = p1;
                }
            }
        } else {
            #pragma unroll
            for (int mi = 0; mi < 4; mi++) {
                int r0 = wm * 64 + mi * 16 + lm;
                int rq0 = qbase + r0, rq1 = rq0 + 8;
                #pragma unroll
                for (int ni = 0; ni < 2; ni++) {
                    int cl = wn * 16 + ni * 8 + 2 * lk;
                    int kc = kt * 64 + cl;
                    float* c = acc[mi][ni];
                    float2 p0, p1;
                    p0.x = (kc     <= rq0)
                         ? rnd_tf32(__expf(c[0]*0.125f)*invl[mi][0]) : 0.f;
                    p0.y = (kc + 1 <= rq0)
                         ? rnd_tf32(__expf(c[1]*0.125f)*invl[mi][0]) : 0.f;
                    p1.x = (kc     <= rq1)
                         ? rnd_tf32(__expf(c[2]*0.125f)*invl[mi][1]) : 0.f;
                    p1.y = (kc + 1 <= rq1)
                         ? rnd_tf32(__expf(c[3]*0.125f)*invl[mi][1]) : 0.f;
                    *(float2*)&Ps[r0 * PPP + cl] = p0;
                    *(float2*)&Ps[(r0 + 8) * PPP + cl] = p1;
                }
            }
        }
        __syncthreads();

        #pragma unroll
        for (int i = 0; i < 8; i++) {
            int idx = tid + i * 256;
            int r = idx >> 4, c4 = idx & 15;
            *(float4*)(weib + (size_t)r * TT + kt * 64 + c4 * 4) =
                *(const float4*)&Ps[r * PPP + c4 * 4];
        }

        #pragma unroll
        for (int ks = 0; ks < 8; ks++) {
            int kb = ks * 8;
            unsigned a[4][4], bfr[2][2];
            #pragma unroll
            for (int mi = 0; mi < 4; mi++) {
                int m = wm * 64 + mi * 16 + lm;
                a[mi][0] = __float_as_uint(Ps[m * PPP + kb + lk]);
                a[mi][1] = __float_as_uint(Ps[(m + 8) * PPP + kb + lk]);
                a[mi][2] = __float_as_uint(Ps[m * PPP + kb + lk + 4]);
                a[mi][3] = __float_as_uint(Ps[(m + 8) * PPP + kb + lk + 4]);
            }
            #pragma unroll
            for (int ni = 0; ni < 2; ni++) {
                int n = wn * 16 + ni * 8 + lm;
                bfr[ni][0] = __float_as_uint(Vs[(kb + lk) * VPP + n]);
                bfr[ni][1] = __float_as_uint(Vs[(kb + lk + 4) * VPP + n]);
            }
            #pragma unroll
            for (int mi = 0; mi < 4; mi++)
                #pragma unroll
                for (int ni = 0; ni < 2; ni++)
                    mma_tf32(oacc[mi][ni], a[mi], bfr[ni]);
        }
    }

    int kend4 = nkt * 16;
    float4 z4 = make_float4(0.f, 0.f, 0.f, 0.f);
    for (int r = tid >> 4; r < 128; r += 16)
        for (int c4 = kend4 + (tid & 15); c4 < TT / 4; c4 += 16)
            *(float4*)(weib + (size_t)r * TT + c4 * 4) = z4;

    float* attnb = attn + ((size_t)b * TT + qbase) * EE + h * HS;
    #pragma unroll
    for (int mi = 0; mi < 4; mi++) {
        int r0 = wm * 64 + mi * 16 + lm;
        #pragma unroll
        for (int ni = 0; ni < 2; ni++) {
            int col = wn * 16 + ni * 8 + 2 * lk;
            *(float2*)(attnb + (size_t)r0 * EE + col) =
                make_float2(rnd_tf32(oacc[mi][ni][0]),
                            rnd_tf32(oacc[mi][ni][1]));
            *(float2*)(attnb + (size_t)(r0 + 8) * EE + col) =
                make_float2(rnd_tf32(oacc[mi][ni][2]),
                            rnd_tf32(oacc[mi][ni][3]));
        }
    }
}

// ---------------- launch ----------------
extern "C" void kernel_launch(void* const* d_in, const int* in_sizes, int n_in,
                              void* d_out, int out_size) {
    const float* x      = (const float*)d_in[0];
    const float* wq     = (const float*)d_in[1];
    const float* wk     = (const float*)d_in[2];
    const float* wv     = (const float*)d_in[3];
    const float* wp     = (const float*)d_in[4];
    const float* bp     = (const float*)d_in[5];
    const float* ln1_g  = (const float*)d_in[6];
    const float* ln1_b  = (const float*)d_in[7];
    const float* ln2_g  = (const float*)d_in[8];
    const float* ln2_b  = (const float*)d_in[9];
    const float* w1     = (const float*)d_in[10];
    const float* b1     = (const float*)d_in[11];
    const float* w2     = (const float*)d_in[12];
    const float* b2     = (const float*)d_in[13];
    const float* w3     = (const float*)d_in[14];
    const float* b3     = (const float*)d_in[15];
    const float* wg_att = (const float*)d_in[16];
    const float* bg_att = (const float*)d_in[17];
    const float* wg_ff  = (const float*)d_in[18];
    const float* bg_ff  = (const float*)d_in[19];

    float* out_x   = (float*)d_out;
    float* out_wei = (float*)d_out + (size_t)ROWS * EE;

    float *h1, *q, *k, *v, *attn, *sa, *x1, *h2, *f1, *f2, *f3, *Lb;
    float *wq_r, *wk_r, *wv_r, *wp_r, *wga_r, *w1_r, *w2_r, *w3_r, *wgf_r;
    cudaGetSymbolAddress((void**)&h1, g_h1);
    cudaGetSymbolAddress((void**)&q,  g_q);
    cudaGetSymbolAddress((void**)&k,  g_k);
    cudaGetSymbolAddress((void**)&v,  g_v);
    cudaGetSymbolAddress((void**)&attn, g_attn);
    cudaGetSymbolAddress((void**)&sa, g_sa);
    cudaGetSymbolAddress((void**)&x1, g_x1);
    cudaGetSymbolAddress((void**)&h2, g_h2);
    cudaGetSymbolAddress((void**)&f1, g_f1);
    cudaGetSymbolAddress((void**)&f2, g_f2);
    cudaGetSymbolAddress((void**)&f3, g_f3);
    cudaGetSymbolAddress((void**)&Lb, g_L);
    cudaGetSymbolAddress((void**)&wq_r,  g_wq_r);
    cudaGetSymbolAddress((void**)&wk_r,  g_wk_r);
    cudaGetSymbolAddress((void**)&wv_r,  g_wv_r);
    cudaGetSymbolAddress((void**)&wp_r,  g_wp_r);
    cudaGetSymbolAddress((void**)&wga_r, g_wga_r);
    cudaGetSymbolAddress((void**)&w1_r,  g_w1_r);
    cudaGetSymbolAddress((void**)&w2_r,  g_w2_r);
    cudaGetSymbolAddress((void**)&w3_r,  g_w3_r);
    cudaGetSymbolAddress((void**)&wgf_r, g_wgf_r);

    // dynamic smem sizes
    int smG64  = STG * (BMM * 20 + BKK * (64 + 8)) * 4;          // 44544
    int smGBig = STG * (BMB * 20 + BKK * (BNB + 8)) * 4;         // 87552
    int smA = (128 * QP + 64 * KPP + 128 * 4) * 4;
    int smB = (128 * QP + 64 * KPP + 64 * VPP + 128 * PPP) * 4;
    cudaFuncSetAttribute(mma_gemm_qkv,
        cudaFuncAttributeMaxDynamicSharedMemorySize, smG64);
    cudaFuncSetAttribute(mma_gemm_big<0,1>,
        cudaFuncAttributeMaxDynamicSharedMemorySize, smGBig);
    cudaFuncSetAttribute(mma_gemm_big<1,1>,
        cudaFuncAttributeMaxDynamicSharedMemorySize, smGBig);
    cudaFuncSetAttribute(mma_gemm_big<2,0>,
        cudaFuncAttributeMaxDynamicSharedMemorySize, smGBig);
    cudaFuncSetAttribute(attn_sum,
        cudaFuncAttributeMaxDynamicSharedMemorySize, smA);
    cudaFuncSetAttribute(attn_out,
        cudaFuncAttributeMaxDynamicSharedMemorySize, smB);

    // 0) pre-round all weights to tf32
    {
        int n1 = HH * EE * HS / 4;
        cvt_tf32_kernel<<<n1 / 256, 256>>>(wq, wq_r, n1);
        cvt_tf32_kernel<<<n1 / 256, 256>>>(wk, wk_r, n1);
        cvt_tf32_kernel<<<n1 / 256, 256>>>(wv, wv_r, n1);
        int n2 = EE * EE / 4;
        cvt_tf32_kernel<<<n2 / 256, 256>>>(wp, wp_r, n2);
        cvt_tf32_kernel<<<n2 / 256, 256>>>(wg_att, wga_r, n2);
        cvt_tf32_kernel<<<n2 / 256, 256>>>(wg_ff, wgf_r, n2);
        int n3 = EE * 4 * EE / 4;
        cvt_tf32_kernel<<<n3 / 256, 256>>>(w1, w1_r, n3);
        int n4 = 4 * EE * 2 * EE / 4;
        cvt_tf32_kernel<<<n4 / 256, 256>>>(w2, w2_r, n4);
        int n5 = 2 * EE * EE / 4;
        cvt_tf32_kernel<<<n5 / 256, 256>>>(w3, w3_r, n5);
    }

    // 1) h1 = LN1(x)
    ln_kernel<<<ROWS, 256>>>(x, ln1_g, ln1_b, h1);

    // 2) fused q/k/v: z = 48
    size_t wStrideZ = (size_t)EE * HS;
    size_t cStrideZ = (size_t)ROWS * HS;
    mma_gemm_qkv<<<dim3(1, ROWS/BMM, 48), 128, smG64>>>(h1, wq_r, wk_r, wv_r,
        q, k, v, EE, wStrideZ, cStrideZ);

    // 3) attention
    attn_sum<<<dim3(TT/128, BB*HH), 256, smA>>>(q, k, Lb);
    attn_out<<<dim3(TT/128, BB*HH), 256, smB>>>(q, k, v, Lb, out_wei, attn);

    // 4) sa = attn @ wp + bp   (rounded)
    mma_gemm_big<0,1><<<dim3(EE/BNB, ROWS/BMB), 256, smGBig>>>(attn, wp_r,
        bp, sa, ROWS, EE, EE, nullptr, nullptr);

    // 5) x1 = sa + sigmoid(sa @ wg_att + bg_att) * x
    mma_gemm_big<2,0><<<dim3(EE/BNB, ROWS/BMB), 256, smGBig>>>(sa, wga_r,
        bg_att, x1, ROWS, EE, EE, sa, x);

    // 6) h2 = LN2(x1)
    ln_kernel<<<ROWS, 256>>>(x1, ln2_g, ln2_b, h2);

    // 7) f1 = gelu(h2 @ w1 + b1)
    mma_gemm_big<1,1><<<dim3(4*EE/BNB, ROWS/BMB), 256, smGBig>>>(h2, w1_r,
        b1, f1, ROWS, 4*EE, EE, nullptr, nullptr);

    // 8) f2 = gelu(f1 @ w2 + b2), K=4096
    mma_gemm_big<1,1><<<dim3(2*EE/BNB, ROWS/BMB), 256, smGBig>>>(f1, w2_r,
        b2, f2, ROWS, 2*EE, 4*EE, nullptr, nullptr);

    // 9) f3 = f2 @ w3 + b3, K=2048
    mma_gemm_big<0,1><<<dim3(EE/BNB, ROWS/BMB), 256, smGBig>>>(f2, w3_r,
        b3, f3, ROWS, EE, 2*EE, nullptr, nullptr);

    // 10) out_x = f3 + sigmoid(f3 @ wg_ff + bg_ff) * x1   (K = E)
    mma_gemm_big<2,0><<<dim3(EE/BNB, ROWS/BMB), 256, smGBig>>>(f3, wgf_r,
        bg_ff, out_x, ROWS, EE, EE, f3, x1);
}

// round 17
// speedup vs baseline: 1.5831x; 1.5831x over previous
#include <cuda_runtime.h>
#include <cuda_fp16.h>
#include <math.h>

// Problem constants
#define BB   2
#define TT   2048
#define EE   1024
#define HH   16
#define HS   64
#define ROWS (BB*TT)          // 4096

// ---------------- device scratch ----------------
__device__ __half g_h1[ROWS*EE];
__device__ float  g_q [ROWS*EE];
__device__ float  g_k [ROWS*EE];
__device__ float  g_v [ROWS*EE];
__device__ __half g_attn[ROWS*EE];
__device__ __half g_sa [ROWS*EE];
__device__ float  g_x1 [ROWS*EE];
__device__ __half g_h2 [ROWS*EE];
__device__ __half g_f1 [ROWS*4*EE];
__device__ __half g_f2 [ROWS*2*EE];
__device__ __half g_f3 [ROWS*EE];
__device__ float  g_L  [BB*HH*TT];
// fp16 TRANSPOSED weights ([N][K], K contiguous)
__device__ __half g_wq_h [HH*EE*HS];
__device__ __half g_wk_h [HH*EE*HS];
__device__ __half g_wv_h [HH*EE*HS];
__device__ __half g_wp_h [EE*EE];
__device__ __half g_wga_h[EE*EE];
__device__ __half g_w1_h [EE*4*EE];
__device__ __half g_w2_h [4*EE*2*EE];
__device__ __half g_w3_h [2*EE*EE];
__device__ __half g_wgf_h[EE*EE];

// ---------------- helpers ----------------
__device__ __forceinline__ unsigned f2tf32(float f) {
    unsigned u;
    asm("cvt.rna.tf32.f32 %0, %1;" : "=r"(u) : "f"(f));
    return u;
}
__device__ __forceinline__ float rnd_tf32(float f) {
    return __uint_as_float(f2tf32(f));
}

__device__ __forceinline__ void mma_tf32(float* c, const unsigned* a,
                                         const unsigned* b) {
    asm volatile(
        "mma.sync.aligned.m16n8k8.row.col.f32.tf32.tf32.f32 "
        "{%0,%1,%2,%3}, {%4,%5,%6,%7}, {%8,%9}, {%0,%1,%2,%3};"
        : "+f"(c[0]), "+f"(c[1]), "+f"(c[2]), "+f"(c[3])
        : "r"(a[0]), "r"(a[1]), "r"(a[2]), "r"(a[3]),
          "r"(b[0]), "r"(b[1]));
}

__device__ __forceinline__ void mma_f16(float* c, const unsigned* a,
                                        const unsigned* b) {
    asm volatile(
        "mma.sync.aligned.m16n8k16.row.col.f32.f16.f16.f32 "
        "{%0,%1,%2,%3}, {%4,%5,%6,%7}, {%8,%9}, {%0,%1,%2,%3};"
        : "+f"(c[0]), "+f"(c[1]), "+f"(c[2]), "+f"(c[3])
        : "r"(a[0]), "r"(a[1]), "r"(a[2]), "r"(a[3]),
          "r"(b[0]), "r"(b[1]));
}

__device__ __forceinline__ void cp_async16(void* smem_dst, const void* gsrc) {
    unsigned s = (unsigned)__cvta_generic_to_shared(smem_dst);
    asm volatile("cp.async.cg.shared.global [%0], [%1], 16;"
                 :: "r"(s), "l"(gsrc));
}
#define CP_COMMIT() asm volatile("cp.async.commit_group;" ::: "memory")
#define CP_WAIT0()  asm volatile("cp.async.wait_group 0;" ::: "memory")
#define CP_WAIT1()  asm volatile("cp.async.wait_group 1;" ::: "memory")

// ---------------- weight transpose + fp16 convert ----------------
// in float [batch][R][C] -> out half [batch][C][R]
__global__ void tpose_h(const float* __restrict__ in,
                        __half* __restrict__ out, int R, int C) {
    __shared__ float t[32][33];
    const float* ip = in  + (size_t)blockIdx.z * R * C;
    __half*      op = out + (size_t)blockIdx.z * R * C;
    int x0 = blockIdx.x * 32, y0 = blockIdx.y * 32;
    #pragma unroll
    for (int j = 0; j < 4; j++)
        t[threadIdx.y + j*8][threadIdx.x] =
            ip[(size_t)(y0 + threadIdx.y + j*8) * C + x0 + threadIdx.x];
    __syncthreads();
    #pragma unroll
    for (int j = 0; j < 4; j++)
        op[(size_t)(x0 + threadIdx.y + j*8) * R + y0 + threadIdx.x] =
            __float2half_rn(t[threadIdx.x][threadIdx.y + j*8]);
}

// ---------------- LayerNorm (fp16 output) ----------------
__global__ void ln_kernel(const float* __restrict__ x,
                          const float* __restrict__ g,
                          const float* __restrict__ b,
                          __half* __restrict__ out) {
    int row = blockIdx.x;
    int tid = threadIdx.x;
    const float* xr = x + (size_t)row * EE;
    float4 v = *(const float4*)(xr + tid * 4);
    float s  = v.x + v.y + v.z + v.w;
    float ss = v.x*v.x + v.y*v.y + v.z*v.z + v.w*v.w;
    __shared__ float sm[32], sm2[32];
    int lane = tid & 31, warp = tid >> 5;
    #pragma unroll
    for (int o = 16; o > 0; o >>= 1) {
        s  += __shfl_down_sync(0xffffffffu, s,  o);
        ss += __shfl_down_sync(0xffffffffu, ss, o);
    }
    if (lane == 0) { sm[warp] = s; sm2[warp] = ss; }
    __syncthreads();
    if (warp == 0) {
        float a = (lane < 8) ? sm[lane]  : 0.f;
        float c = (lane < 8) ? sm2[lane] : 0.f;
        #pragma unroll
        for (int o = 4; o > 0; o >>= 1) {
            a += __shfl_down_sync(0xffffffffu, a, o);
            c += __shfl_down_sync(0xffffffffu, c, o);
        }
        if (lane == 0) { sm[0] = a; sm2[0] = c; }
    }
    __syncthreads();
    float mu  = sm[0]  * (1.0f / EE);
    float var = sm2[0] * (1.0f / EE) - mu * mu;
    float rstd = rsqrtf(var + 1e-5f);
    float4 gg = *(const float4*)(g + tid * 4);
    float4 bb = *(const float4*)(b + tid * 4);
    __half2* op = (__half2*)(out + (size_t)row * EE + tid * 4);
    op[0] = __floats2half2_rn((v.x - mu) * rstd * gg.x + bb.x,
                              (v.y - mu) * rstd * gg.y + bb.y);
    op[1] = __floats2half2_rn((v.z - mu) * rstd * gg.z + bb.z,
                              (v.w - mu) * rstd * gg.w + bb.w);
}

// ================== fp16 MMA GEMM ==================
// BM=128, BN=128, BK=32 (2 x k16), 256 thr, 8 warps (2M x 4N), warp 64x32.
// A [M][K] half, B [N][K] half (both K-contiguous). 3-stage cp.async.
// EPI: 0 bias, 1 gelu+bias, 2 other(half) + sigmoid(+bias)*resid(float)
// QKV: z selects B0/B1/B2 and C0/C1/C2; output col remapped per-head, fp32.
// COUT: 0 = half, 1 = float, 2 = float tf32-rounded
#define HBM 128
#define HBN 128
#define HBK 32
#define APH 40            // smem pitch in halves (32 + 8)
#define STG 3

template<int EPI, int QKV, int COUT>
__global__ void __launch_bounds__(256, 2)
hgemm(const __half* __restrict__ A,
      const __half* __restrict__ B0, const __half* __restrict__ B1,
      const __half* __restrict__ B2,
      const float* __restrict__ bias,
      void* C0v, void* C1v, void* C2v,
      int M, int N, int K, size_t cStrideZ,
      const __half* __restrict__ other, const float* __restrict__ resid) {
    constexpr int ASZH = HBM * APH;       // halves per A stage
    constexpr int BSZH = HBN * APH;

    extern __shared__ __half hsm[];
    __half* As = hsm;
    __half* Bs = hsm + STG * ASZH;

    int which = QKV ? blockIdx.z : 0;
    const __half* Bp = (which == 0) ? B0 : ((which == 1) ? B1 : B2);

    int m0 = blockIdx.y * HBM, n0 = blockIdx.x * HBN;
    int tid  = threadIdx.x;
    int lane = tid & 31, warp = tid >> 5;
    int wm = warp >> 2, wn = warp & 3;
    int lm = lane >> 2, lk = lane & 3;

    float acc[4][4][4];
    #pragma unroll
    for (int i = 0; i < 4; i++)
        #pragma unroll
        for (int j = 0; j < 4; j++)
            #pragma unroll
            for (int l = 0; l < 4; l++) acc[i][j][l] = 0.f;

    auto stage = [&](int s, int k0) {
        #pragma unroll
        for (int i = 0; i < 2; i++) {          // A: 512 16B chunks
            int idx = tid + i * 256;
            int r = idx >> 2, c = idx & 3;
            cp_async16(&As[s * ASZH + r * APH + c * 8],
                       A + (size_t)(m0 + r) * K + k0 + c * 8);
        }
        #pragma unroll
        for (int i = 0; i < 2; i++) {          // B: 512 16B chunks
            int idx = tid + i * 256;
            int r = idx >> 2, c = idx & 3;
            cp_async16(&Bs[s * BSZH + r * APH + c * 8],
                       Bp + (size_t)(n0 + r) * K + k0 + c * 8);
        }
    };

    int nk = K / HBK;                          // >= 32
    stage(0, 0); CP_COMMIT();
    stage(1, HBK); CP_COMMIT();

    for (int it = 0; it < nk; it++) {
        CP_WAIT1();
        __syncthreads();
        if (it + 2 < nk) stage((it + 2) % STG, (it + 2) * HBK);
        CP_COMMIT();

        const __half* Asb = As + (it % STG) * ASZH;
        const __half* Bsb = Bs + (it % STG) * BSZH;
        #pragma unroll
        for (int ks = 0; ks < 2; ks++) {       // 2 x k16
            int kb = ks * 16;
            unsigned a[4][4], b[4][2];
            #pragma unroll
            for (int mi = 0; mi < 4; mi++) {
                int m = wm * 64 + mi * 16 + lm;
                a[mi][0] = *(const unsigned*)&Asb[m * APH + kb + lk * 2];
                a[mi][1] = *(const unsigned*)&Asb[(m + 8) * APH + kb + lk * 2];
                a[mi][2] = *(const unsigned*)&Asb[m * APH + kb + lk * 2 + 8];
                a[mi][3] = *(const unsigned*)&Asb[(m + 8) * APH + kb + lk*2 + 8];
            }
            #pragma unroll
            for (int ni = 0; ni < 4; ni++) {
                int n = wn * 32 + ni * 8 + lm;
                b[ni][0] = *(const unsigned*)&Bsb[n * APH + kb + lk * 2];
                b[ni][1] = *(const unsigned*)&Bsb[n * APH + kb + lk * 2 + 8];
            }
            #pragma unroll
            for (int mi = 0; mi < 4; mi++)
                #pragma unroll
                for (int ni = 0; ni < 4; ni++)
                    mma_f16(acc[mi][ni], a[mi], b[ni]);
        }
    }

    // ---------------- epilogue ----------------
    int gm = m0 + wm * 64;
    int gn = n0 + wn * 32;
    #pragma unroll
    for (int mi = 0; mi < 4; mi++) {
        #pragma unroll
        for (int hf = 0; hf < 2; hf++) {
            int row = gm + mi * 16 + lm + hf * 8;
            #pragma unroll
            for (int ni = 0; ni < 4; ni++) {
                int col = gn + ni * 8 + lk * 2;
                float v0 = acc[mi][ni][hf * 2 + 0];
                float v1 = acc[mi][ni][hf * 2 + 1];
                if (bias) { v0 += bias[col]; v1 += bias[col + 1]; }
                float o0, o1;
                if (EPI == 0) {
                    o0 = v0; o1 = v1;
                } else if (EPI == 1) {
                    o0 = 0.5f * v0 * (1.0f + erff(v0 * 0.70710678118654752f));
                    o1 = 0.5f * v1 * (1.0f + erff(v1 * 0.70710678118654752f));
                } else {
                    size_t idx = (size_t)row * N + col;
                    float2 ot = __half22float2(*(const __half2*)(other + idx));
                    float2 rs = *(const float2*)(resid + idx);
                    o0 = ot.x + rs.x / (1.0f + __expf(-v0));
                    o1 = ot.y + rs.y / (1.0f + __expf(-v1));
                }
                if (QKV) {
                    float* Cp = (float*)((which == 0) ? C0v
                                : ((which == 1) ? C1v : C2v));
                    int head = col >> 6;
                    size_t idx = (size_t)head * cStrideZ
                               + (size_t)row * HS + (col & 63);
                    *(float2*)(Cp + idx) =
                        make_float2(rnd_tf32(o0), rnd_tf32(o1));
                } else {
                    size_t idx = (size_t)row * N + col;
                    if (COUT == 0) {
                        *(__half2*)((__half*)C0v + idx) =
                            __floats2half2_rn(o0, o1);
                    } else if (COUT == 1) {
                        *(float2*)((float*)C0v + idx) = make_float2(o0, o1);
                    } else {
                        *(float2*)((float*)C0v + idx) =
                            make_float2(rnd_tf32(o0), rnd_tf32(o1));
                    }
                }
            }
        }
    }
}

// ==================== MMA attention (tf32, unchanged core) ====================
#define QP 68
#define KPP 68
#define VPP 72
#define PPP 68

__device__ __forceinline__ void s_tile_mma(const float* __restrict__ Qs,
                                           const float* __restrict__ Ks,
                                           int wm, int wn, int lane,
                                           float acc[4][2][4]) {
    #pragma unroll
    for (int mi = 0; mi < 4; mi++)
        #pragma unroll
        for (int ni = 0; ni < 2; ni++)
            #pragma unroll
            for (int l = 0; l < 4; l++) acc[mi][ni][l] = 0.f;
    int lm = lane >> 2, lk = lane & 3;
    #pragma unroll
    for (int ks = 0; ks < 8; ks++) {
        int kb = ks * 8;
        unsigned a[4][4], b[2][2];
        #pragma unroll
        for (int mi = 0; mi < 4; mi++) {
            int m = wm * 64 + mi * 16 + lm;
            a[mi][0] = __float_as_uint(Qs[m * QP + kb + lk]);
            a[mi][1] = __float_as_uint(Qs[(m + 8) * QP + kb + lk]);
            a[mi][2] = __float_as_uint(Qs[m * QP + kb + lk + 4]);
            a[mi][3] = __float_as_uint(Qs[(m + 8) * QP + kb + lk + 4]);
        }
        #pragma unroll
        for (int ni = 0; ni < 2; ni++) {
            int n = wn * 16 + ni * 8 + lm;
            b[ni][0] = __float_as_uint(Ks[n * KPP + kb + lk]);
            b[ni][1] = __float_as_uint(Ks[n * KPP + kb + lk + 4]);
        }
        #pragma unroll
        for (int mi = 0; mi < 4; mi++)
            #pragma unroll
            for (int ni = 0; ni < 2; ni++)
                mma_tf32(acc[mi][ni], a[mi], b[ni]);
    }
}

__global__ void __launch_bounds__(256)
attn_sum(const float* __restrict__ q, const float* __restrict__ k,
         float* __restrict__ Lb) {
    extern __shared__ float sm[];
    float* Qs   = sm;
    float* Ks   = sm + 128 * QP;
    float* Lred = Ks + 64 * KPP;

    int bh = blockIdx.y;
    int qt = (int)(gridDim.x - 1) - (int)blockIdx.x;
    int b = bh >> 4, h = bh & 15;
    int qbase = qt * 128;
    const float* qg = q + ((size_t)h * ROWS + (size_t)b * TT + qbase) * HS;
    const float* kg = k + ((size_t)h * ROWS + (size_t)b * TT) * HS;

    int tid = threadIdx.x;
    int lane = tid & 31, warp = tid >> 5;
    int wm = warp >> 2, wn = warp & 3;
    int lm = lane >> 2, lk = lane & 3;

    #pragma unroll
    for (int i = 0; i < 8; i++) {
        int idx = tid + i * 256;
        int r = idx >> 4, c4 = idx & 15;
        cp_async16(&Qs[r * QP + c4 * 4], qg + (size_t)r * HS + c4 * 4);
    }
    CP_COMMIT();
    CP_WAIT0();
    __syncthreads();

    float lsum[4][2];
    #pragma unroll
    for (int mi = 0; mi < 4; mi++) { lsum[mi][0] = 0.f; lsum[mi][1] = 0.f; }

    int nkt = 2 * qt + 2;
    for (int kt = 0; kt < nkt; kt++) {
        __syncthreads();
        #pragma unroll
        for (int i = 0; i < 4; i++) {
            int idx = tid + i * 256;
            int r = idx >> 4, c4 = idx & 15;
            cp_async16(&Ks[r * KPP + c4 * 4],
                       kg + (size_t)(kt * 64 + r) * HS + c4 * 4);
        }
        CP_COMMIT();
        CP_WAIT0();
        __syncthreads();

        float acc[4][2][4];
        s_tile_mma(Qs, Ks, wm, wn, lane, acc);
        if (kt < 2 * qt) {
            #pragma unroll
            for (int mi = 0; mi < 4; mi++)
                #pragma unroll
                for (int ni = 0; ni < 2; ni++) {
                    float* c = acc[mi][ni];
                    lsum[mi][0] += __expf(c[0] * 0.125f)
                                 + __expf(c[1] * 0.125f);
                    lsum[mi][1] += __expf(c[2] * 0.125f)
                                 + __expf(c[3] * 0.125f);
                }
        } else {
            #pragma unroll
            for (int mi = 0; mi < 4; mi++) {
                int rq = qbase + wm * 64 + mi * 16 + lm;
                #pragma unroll
                for (int ni = 0; ni < 2; ni++) {
                    int kc = kt * 64 + wn * 16 + ni * 8 + 2 * lk;
                    float* c = acc[mi][ni];
                    if (kc     <= rq)     lsum[mi][0] += __expf(c[0] * 0.125f);
                    if (kc + 1 <= rq)     lsum[mi][0] += __expf(c[1] * 0.125f);
                    if (kc     <= rq + 8) lsum[mi][1] += __expf(c[2] * 0.125f);
                    if (kc + 1 <= rq + 8) lsum[mi][1] += __expf(c[3] * 0.125f);
                }
            }
        }
    }

    #pragma unroll
    for (int mi = 0; mi < 4; mi++)
        #pragma unroll
        for (int hf = 0; hf < 2; hf++) {
            float v = lsum[mi][hf];
            v += __shfl_xor_sync(0xffffffffu, v, 1);
            v += __shfl_xor_sync(0xffffffffu, v, 2);
            if (lk == 0)
                Lred[(wm * 64 + mi * 16 + lm + hf * 8) * 4 + wn] = v;
        }
    __syncthreads();
    if (tid < 128) {
        float l = Lred[tid * 4] + Lred[tid * 4 + 1] +
                  Lred[tid * 4 + 2] + Lred[tid * 4 + 3];
        Lb[(size_t)bh * TT + qbase + tid] = l;
    }
}

__global__ void __launch_bounds__(256)
attn_out(const float* __restrict__ q, const float* __restrict__ k,
         const float* __restrict__ v, const float* __restrict__ Lb,
         float* __restrict__ wei, __half* __restrict__ attn) {
    extern __shared__ float sm[];
    float* Qs = sm;
    float* Ks = Qs + 128 * QP;
    float* Vs = Ks + 64 * KPP;
    float* Ps = Vs + 64 * VPP;

    int bh = blockIdx.y;
    int qt = (int)(gridDim.x - 1) - (int)blockIdx.x;
    int b = bh >> 4, h = bh & 15;
    int qbase = qt * 128;
    const float* qg = q + ((size_t)h * ROWS + (size_t)b * TT + qbase) * HS;
    const float* kg = k + ((size_t)h * ROWS + (size_t)b * TT) * HS;
    const float* vg = v + ((size_t)h * ROWS + (size_t)b * TT) * HS;
    float* weib = wei + ((size_t)bh * TT + qbase) * TT;

    int tid = threadIdx.x;
    int lane = tid & 31, warp = tid >> 5;
    int wm = warp >> 2, wn = warp & 3;
    int lm = lane >> 2, lk = lane & 3;

    #pragma unroll
    for (int i = 0; i < 8; i++) {
        int idx = tid + i * 256;
        int r = idx >> 4, c4 = idx & 15;
        cp_async16(&Qs[r * QP + c4 * 4], qg + (size_t)r * HS + c4 * 4);
    }
    CP_COMMIT();

    float invl[4][2];
    #pragma unroll
    for (int mi = 0; mi < 4; mi++)
        #pragma unroll
        for (int hf = 0; hf < 2; hf++)
            invl[mi][hf] = 1.0f /
                Lb[(size_t)bh * TT + qbase + wm * 64 + mi * 16 + lm + hf * 8];

    float oacc[4][2][4];
    #pragma unroll
    for (int mi = 0; mi < 4; mi++)
        #pragma unroll
        for (int ni = 0; ni < 2; ni++)
            #pragma unroll
            for (int l = 0; l < 4; l++) oacc[mi][ni][l] = 0.f;

    CP_WAIT0();
    __syncthreads();

    int nkt = 2 * qt + 2;
    for (int kt = 0; kt < nkt; kt++) {
        __syncthreads();
        #pragma unroll
        for (int i = 0; i < 4; i++) {
            int idx = tid + i * 256;
            int r = idx >> 4, c4 = idx & 15;
            cp_async16(&Ks[r * KPP + c4 * 4],
                       kg + (size_t)(kt * 64 + r) * HS + c4 * 4);
            cp_async16(&Vs[r * VPP + c4 * 4],
                       vg + (size_t)(kt * 64 + r) * HS + c4 * 4);
        }
        CP_COMMIT();
        CP_WAIT0();
        __syncthreads();

        float acc[4][2][4];
        s_tile_mma(Qs, Ks, wm, wn, lane, acc);

        if (kt < 2 * qt) {
            #pragma unroll
            for (int mi = 0; mi < 4; mi++) {
                int r0 = wm * 64 + mi * 16 + lm;
                #pragma unroll
                for (int ni = 0; ni < 2; ni++) {
                    int cl = wn * 16 + ni * 8 + 2 * lk;
                    float* c = acc[mi][ni];
                    float2 p0, p1;
                    p0.x = rnd_tf32(__expf(c[0] * 0.125f) * invl[mi][0]);
                    p0.y = rnd_tf32(__expf(c[1] * 0.125f) * invl[mi][0]);
                    p1.x = rnd_tf32(__expf(c[2] * 0.125f) * invl[mi][1]);
                    p1.y = rnd_tf32(__expf(c[3] * 0.125f) * invl[mi][1]);
                    *(float2*)&Ps[r0 * PPP + cl] = p0;
                    *(float2*)&Ps[(r0 + 8) * PPP + cl] = p1;
                }
            }
        } else {
            #pragma unroll
            for (int mi = 0; mi < 4; mi++) {
                int r0 = wm * 64 + mi * 16 + lm;
                int rq0 = qbase + r0, rq1 = rq0 + 8;
                #pragma unroll
                for (int ni = 0; ni < 2; ni++) {
                    int cl = wn * 16 + ni * 8 + 2 * lk;
                    int kc = kt * 64 + cl;
                    float* c = acc[mi][ni];
                    float2 p0, p1;
                    p0.x = (kc     <= rq0)
                         ? rnd_tf32(__expf(c[0]*0.125f)*invl[mi][0]) : 0.f;
                    p0.y = (kc + 1 <= rq0)
                         ? rnd_tf32(__expf(c[1]*0.125f)*invl[mi][0]) : 0.f;
                    p1.x = (kc     <= rq1)
                         ? rnd_tf32(__expf(c[2]*0.125f)*invl[mi][1]) : 0.f;
                    p1.y = (kc + 1 <= rq1)
                         ? rnd_tf32(__expf(c[3]*0.125f)*invl[mi][1]) : 0.f;
                    *(float2*)&Ps[r0 * PPP + cl] = p0;
                    *(float2*)&Ps[(r0 + 8) * PPP + cl] = p1;
                }
            }
        }
        __syncthreads();

        #pragma unroll
        for (int i = 0; i < 8; i++) {
            int idx = tid + i * 256;
            int r = idx >> 4, c4 = idx & 15;
            *(float4*)(weib + (size_t)r * TT + kt * 64 + c4 * 4) =
                *(const float4*)&Ps[r * PPP + c4 * 4];
        }

        #pragma unroll
        for (int ks = 0; ks < 8; ks++) {
            int kb = ks * 8;
            unsigned a[4][4], bfr[2][2];
            #pragma unroll
            for (int mi = 0; mi < 4; mi++) {
                int m = wm * 64 + mi * 16 + lm;
                a[mi][0] = __float_as_uint(Ps[m * PPP + kb + lk]);
                a[mi][1] = __float_as_uint(Ps[(m + 8) * PPP + kb + lk]);
                a[mi][2] = __float_as_uint(Ps[m * PPP + kb + lk + 4]);
                a[mi][3] = __float_as_uint(Ps[(m + 8) * PPP + kb + lk + 4]);
            }
            #pragma unroll
            for (int ni = 0; ni < 2; ni++) {
                int n = wn * 16 + ni * 8 + lm;
                bfr[ni][0] = __float_as_uint(Vs[(kb + lk) * VPP + n]);
                bfr[ni][1] = __float_as_uint(Vs[(kb + lk + 4) * VPP + n]);
            }
            #pragma unroll
            for (int mi = 0; mi < 4; mi++)
                #pragma unroll
                for (int ni = 0; ni < 2; ni++)
                    mma_tf32(oacc[mi][ni], a[mi], bfr[ni]);
        }
    }

    int kend4 = nkt * 16;
    float4 z4 = make_float4(0.f, 0.f, 0.f, 0.f);
    for (int r = tid >> 4; r < 128; r += 16)
        for (int c4 = kend4 + (tid & 15); c4 < TT / 4; c4 += 16)
            *(float4*)(weib + (size_t)r * TT + c4 * 4) = z4;

    // write attn output as fp16 (feeds proj GEMM A-operand)
    __half* attnb = attn + ((size_t)b * TT + qbase) * EE + h * HS;
    #pragma unroll
    for (int mi = 0; mi < 4; mi++) {
        int r0 = wm * 64 + mi * 16 + lm;
        #pragma unroll
        for (int ni = 0; ni < 2; ni++) {
            int col = wn * 16 + ni * 8 + 2 * lk;
            *(__half2*)(attnb + (size_t)r0 * EE + col) =
                __floats2half2_rn(oacc[mi][ni][0], oacc[mi][ni][1]);
            *(__half2*)(attnb + (size_t)(r0 + 8) * EE + col) =
                __floats2half2_rn(oacc[mi][ni][2], oacc[mi][ni][3]);
        }
    }
}

// ---------------- launch ----------------
extern "C" void kernel_launch(void* const* d_in, const int* in_sizes, int n_in,
                              void* d_out, int out_size) {
    const float* x      = (const float*)d_in[0];
    const float* wq     = (const float*)d_in[1];
    const float* wk     = (const float*)d_in[2];
    const float* wv     = (const float*)d_in[3];
    const float* wp     = (const float*)d_in[4];
    const float* bp     = (const float*)d_in[5];
    const float* ln1_g  = (const float*)d_in[6];
    const float* ln1_b  = (const float*)d_in[7];
    const float* ln2_g  = (const float*)d_in[8];
    const float* ln2_b  = (const float*)d_in[9];
    const float* w1     = (const float*)d_in[10];
    const float* b1     = (const float*)d_in[11];
    const float* w2     = (const float*)d_in[12];
    const float* b2     = (const float*)d_in[13];
    const float* w3     = (const float*)d_in[14];
    const float* b3     = (const float*)d_in[15];
    const float* wg_att = (const float*)d_in[16];
    const float* bg_att = (const float*)d_in[17];
    const float* wg_ff  = (const float*)d_in[18];
    const float* bg_ff  = (const float*)d_in[19];

    float* out_x   = (float*)d_out;
    float* out_wei = (float*)d_out + (size_t)ROWS * EE;

    __half *h1, *h2, *attn, *sa, *f1, *f2, *f3;
    float *q, *k, *v, *x1, *Lb;
    __half *wq_h, *wk_h, *wv_h, *wp_h, *wga_h, *w1_h, *w2_h, *w3_h, *wgf_h;
    cudaGetSymbolAddress((void**)&h1, g_h1);
    cudaGetSymbolAddress((void**)&q,  g_q);
    cudaGetSymbolAddress((void**)&k,  g_k);
    cudaGetSymbolAddress((void**)&v,  g_v);
    cudaGetSymbolAddress((void**)&attn, g_attn);
    cudaGetSymbolAddress((void**)&sa, g_sa);
    cudaGetSymbolAddress((void**)&x1, g_x1);
    cudaGetSymbolAddress((void**)&h2, g_h2);
    cudaGetSymbolAddress((void**)&f1, g_f1);
    cudaGetSymbolAddress((void**)&f2, g_f2);
    cudaGetSymbolAddress((void**)&f3, g_f3);
    cudaGetSymbolAddress((void**)&Lb, g_L);
    cudaGetSymbolAddress((void**)&wq_h,  g_wq_h);
    cudaGetSymbolAddress((void**)&wk_h,  g_wk_h);
    cudaGetSymbolAddress((void**)&wv_h,  g_wv_h);
    cudaGetSymbolAddress((void**)&wp_h,  g_wp_h);
    cudaGetSymbolAddress((void**)&wga_h, g_wga_h);
    cudaGetSymbolAddress((void**)&w1_h,  g_w1_h);
    cudaGetSymbolAddress((void**)&w2_h,  g_w2_h);
    cudaGetSymbolAddress((void**)&w3_h,  g_w3_h);
    cudaGetSymbolAddress((void**)&wgf_h, g_wgf_h);

    int smG = STG * (HBM * APH + HBN * APH) * 2;     // 61440 bytes
    int smA = (128 * QP + 64 * KPP + 128 * 4) * 4;
    int smB = (128 * QP + 64 * KPP + 64 * VPP + 128 * PPP) * 4;
    cudaFuncSetAttribute(hgemm<0,1,2>,
        cudaFuncAttributeMaxDynamicSharedMemorySize, smG);
    cudaFuncSetAttribute(hgemm<0,0,0>,
        cudaFuncAttributeMaxDynamicSharedMemorySize, smG);
    cudaFuncSetAttribute(hgemm<1,0,0>,
        cudaFuncAttributeMaxDynamicSharedMemorySize, smG);
    cudaFuncSetAttribute(hgemm<2,0,1>,
        cudaFuncAttributeMaxDynamicSharedMemorySize, smG);
    cudaFuncSetAttribute(attn_sum,
        cudaFuncAttributeMaxDynamicSharedMemorySize, smA);
    cudaFuncSetAttribute(attn_out,
        cudaFuncAttributeMaxDynamicSharedMemorySize, smB);

    // 0) transpose + fp16-convert all weights ([R][C] -> [C][R])
    dim3 tb(32, 8);
    tpose_h<<<dim3(HS/32, EE/32, HH), tb>>>(wq, wq_h, EE, HS);
    tpose_h<<<dim3(HS/32, EE/32, HH), tb>>>(wk, wk_h, EE, HS);
    tpose_h<<<dim3(HS/32, EE/32, HH), tb>>>(wv, wv_h, EE, HS);
    tpose_h<<<dim3(EE/32, EE/32, 1), tb>>>(wp, wp_h, EE, EE);
    tpose_h<<<dim3(EE/32, EE/32, 1), tb>>>(wg_att, wga_h, EE, EE);
    tpose_h<<<dim3(EE/32, EE/32, 1), tb>>>(wg_ff, wgf_h, EE, EE);
    tpose_h<<<dim3(4*EE/32, EE/32, 1), tb>>>(w1, w1_h, EE, 4*EE);
    tpose_h<<<dim3(2*EE/32, 4*EE/32, 1), tb>>>(w2, w2_h, 4*EE, 2*EE);
    tpose_h<<<dim3(EE/32, 2*EE/32, 1), tb>>>(w3, w3_h, 2*EE, EE);

    // 1) h1 = LN1(x)  (fp16)
    ln_kernel<<<ROWS, 256>>>(x, ln1_g, ln1_b, h1);

    // 2) q/k/v: one [4096 x 1024 x 1024] fp16 GEMM per weight (z = 3),
    //    per-head column remap in epilogue, outputs tf32-rounded fp32.
    size_t cStrideZ = (size_t)ROWS * HS;
    hgemm<0,1,2><<<dim3(EE/HBN, ROWS/HBM, 3), 256, smG>>>(h1,
        wq_h, wk_h, wv_h, nullptr, q, k, v,
        ROWS, EE, EE, cStrideZ, nullptr, nullptr);

    // 3) attention (tf32 MMA, unchanged; writes attn fp16)
    attn_sum<<<dim3(TT/128, BB*HH), 256, smA>>>(q, k, Lb);
    attn_out<<<dim3(TT/128, BB*HH), 256, smB>>>(q, k, v, Lb, out_wei, attn);

    // 4) sa = attn @ wp + bp     (fp16 out)
    hgemm<0,0,0><<<dim3(EE/HBN, ROWS/HBM, 1), 256, smG>>>(attn,
        wp_h, nullptr, nullptr, bp, sa, nullptr, nullptr,
        ROWS, EE, EE, 0, nullptr, nullptr);

    // 5) x1 = sa + sigmoid(sa @ wg_att + bg_att) * x   (fp32 out)
    hgemm<2,0,1><<<dim3(EE/HBN, ROWS/HBM, 1), 256, smG>>>(sa,
        wga_h, nullptr, nullptr, bg_att, x1, nullptr, nullptr,
        ROWS, EE, EE, 0, sa, x);

    // 6) h2 = LN2(x1)  (fp16)
    ln_kernel<<<ROWS, 256>>>(x1, ln2_g, ln2_b, h2);

    // 7) f1 = gelu(h2 @ w1 + b1)   [4096 x 4096]  (fp16)
    hgemm<1,0,0><<<dim3(4*EE/HBN, ROWS/HBM, 1), 256, smG>>>(h2,
        w1_h, nullptr, nullptr, b1, f1, nullptr, nullptr,
        ROWS, 4*EE, EE, 0, nullptr, nullptr);

    // 8) f2 = gelu(f1 @ w2 + b2)   [4096 x 2048], K=4096  (fp16)
    hgemm<1,0,0><<<dim3(2*EE/HBN, ROWS/HBM, 1), 256, smG>>>(f1,
        w2_h, nullptr, nullptr, b2, f2, nullptr, nullptr,
        ROWS, 2*EE, 4*EE, 0, nullptr, nullptr);

    // 9) f3 = f2 @ w3 + b3         [4096 x 1024], K=2048  (fp16)
    hgemm<0,0,0><<<dim3(EE/HBN, ROWS/HBM, 1), 256, smG>>>(f2,
        w3_h, nullptr, nullptr, b3, f3, nullptr, nullptr,
        ROWS, EE, 2*EE, 0, nullptr, nullptr);

    // 10) out_x = f3 + sigmoid(f3 @ wg_ff + bg_ff) * x1   (fp32 out)
    hgemm<2,0,1><<<dim3(EE/HBN, ROWS/HBM, 1), 256, smG>>>(f3,
        wgf_h, nullptr, nullptr, bg_ff, out_x, nullptr, nullptr,
        ROWS, EE, EE, 0, f3, x1);
}